// round 7
// baseline (speedup 1.0000x reference)
#include <cuda_runtime.h>
#include <cuda_bf16.h>

// Problem constants (match reference_code)
#define NN 50000
#define EE 600000
#define FF 128   // F_IN == F_OUT == 128

// Scratch for the scatter-sum result (25.6 MB). Device globals are the
// sanctioned scratch mechanism (no allocations allowed).
__device__ float g_agg[(size_t)NN * FF];

// 1 if edge_index buffer holds int64 elements, 0 if int32. Written by
// detect_kernel each launch (deterministic for fixed input).
__device__ int g_is64;

// ---------------------------------------------------------------------------
// Kernel 0: detect index dtype. Sample odd 32-bit words: if the buffer is
// int64 (values < 50000 => zero high halves), their OR is 0. If int32, the
// odd words are random node ids => OR != 0 with certainty on this dataset.
// ---------------------------------------------------------------------------
__global__ void detect_kernel(const unsigned int* __restrict__ w) {
    __shared__ unsigned int red[256];
    unsigned int acc = 0;
    // Sample indices 1,3,...,4095 — safely inside the buffer under either
    // interpretation (int32: 1.2M words, int64: 2.4M words).
    for (int i = threadIdx.x; i < 2048; i += 256)
        acc |= w[2 * i + 1];
    red[threadIdx.x] = acc;
    __syncthreads();
    for (int s = 128; s > 0; s >>= 1) {
        if (threadIdx.x < s) red[threadIdx.x] |= red[threadIdx.x + s];
        __syncthreads();
    }
    if (threadIdx.x == 0) g_is64 = (red[0] == 0u) ? 1 : 0;
}

// ---------------------------------------------------------------------------
// Kernel 1: zero the aggregation buffer (float4 stores, ~25.6 MB)
// ---------------------------------------------------------------------------
__global__ void zero_kernel(float4* __restrict__ agg4, int n4) {
    int i = blockIdx.x * blockDim.x + threadIdx.x;
    if (i < n4) agg4[i] = make_float4(0.f, 0.f, 0.f, 0.f);
}

// ---------------------------------------------------------------------------
// Kernel 2: edge scatter. One warp per edge.
// Lane l loads x[src][4l..4l+3] (LDG.128) and does a vector reduction
// (red.global.add.v4.f32 — fire-and-forget, no return value) into agg[dst].
// Index dtype chosen at runtime via g_is64; out-of-range edges are skipped
// so no interpretation can fault.
// ---------------------------------------------------------------------------
__global__ void scatter_kernel(const float* __restrict__ x,
                               const void* __restrict__ eiv,
                               float* __restrict__ agg) {
    int warp = (blockIdx.x * blockDim.x + threadIdx.x) >> 5;
    int lane = threadIdx.x & 31;
    if (warp >= EE) return;

    int src, dst;
    if (g_is64) {
        const long long* ei = (const long long*)eiv;
        src = (int)ei[warp];
        dst = (int)ei[(long long)EE + warp];
    } else {
        const int* ei = (const int*)eiv;
        src = ei[warp];
        dst = ei[EE + warp];
    }
    if ((unsigned)src >= NN || (unsigned)dst >= NN) return;  // never on valid data

    const float4* xrow = reinterpret_cast<const float4*>(x + (size_t)src * FF);
    float4 v = xrow[lane];

    float* dp = agg + (size_t)dst * FF + lane * 4;
    asm volatile("red.global.add.v4.f32 [%0], {%1, %2, %3, %4};"
                 :: "l"(dp), "f"(v.x), "f"(v.y), "f"(v.z), "f"(v.w)
                 : "memory");
}

// ---------------------------------------------------------------------------
// Kernel 3: out[N,128] = agg[N,128] @ W2[128,128] + b2
// Block: 256 threads, 64 rows per block.
// Smem: A-tile 64x128 f32 (32 KB) + W2 128x128 f32 (64 KB) = 96 KB dynamic.
// Thread (tx in [0,32), ty in [0,8)):
//   cols   c = 4*tx .. 4*tx+3         (float4-contiguous)
//   rows   r = ty*8 + j, j in [0,8)
// Register tile 8x4, k unrolled by 4 -> 12 LDS.128 per 128 FFMA.
// ---------------------------------------------------------------------------
#define GEMM_ROWS 64

__global__ __launch_bounds__(256, 2)
void gemm_kernel(const float* __restrict__ agg,
                 const float* __restrict__ W2,
                 const float* __restrict__ b2,
                 float* __restrict__ out) {
    extern __shared__ float smem[];
    float* a_s = smem;                    // [64][128]
    float* w_s = smem + GEMM_ROWS * FF;   // [128][128]

    int tid = threadIdx.x;
    int tx  = tid & 31;    // 0..31 -> column quad
    int ty  = tid >> 5;    // 0..7  -> row group
    int row0 = blockIdx.x * GEMM_ROWS;

    // Load A-tile (2048 float4)
    {
        const float4* a4g = reinterpret_cast<const float4*>(agg);
        float4* a4s = reinterpret_cast<float4*>(a_s);
        #pragma unroll
        for (int it = 0; it < (GEMM_ROWS * FF / 4) / 256; it++) {
            int idx = tid + it * 256;
            int r   = idx >> 5;          // /32 float4 per row
            int c4  = idx & 31;
            int gr  = row0 + r;
            float4 v = make_float4(0.f, 0.f, 0.f, 0.f);
            if (gr < NN) v = a4g[(size_t)gr * 32 + c4];
            a4s[idx] = v;
        }
    }
    // Load W2 (4096 float4)
    {
        const float4* w4g = reinterpret_cast<const float4*>(W2);
        float4* w4s = reinterpret_cast<float4*>(w_s);
        #pragma unroll
        for (int it = 0; it < (FF * FF / 4) / 256; it++) {
            int idx = tid + it * 256;
            w4s[idx] = w4g[idx];
        }
    }
    __syncthreads();

    float acc[8][4];
    #pragma unroll
    for (int j = 0; j < 8; j++)
        #pragma unroll
        for (int c = 0; c < 4; c++) acc[j][c] = 0.f;

    const float4* a4s = reinterpret_cast<const float4*>(a_s);
    const float4* w4s = reinterpret_cast<const float4*>(w_s);

    #pragma unroll 4
    for (int k = 0; k < FF; k += 4) {
        float4 wv0 = w4s[(k + 0) * 32 + tx];
        float4 wv1 = w4s[(k + 1) * 32 + tx];
        float4 wv2 = w4s[(k + 2) * 32 + tx];
        float4 wv3 = w4s[(k + 3) * 32 + tx];
        #pragma unroll
        for (int j = 0; j < 8; j++) {
            int r = ty * 8 + j;
            float4 av = a4s[r * 32 + (k >> 2)];  // a[r][k..k+3]
            acc[j][0] += av.x * wv0.x + av.y * wv1.x + av.z * wv2.x + av.w * wv3.x;
            acc[j][1] += av.x * wv0.y + av.y * wv1.y + av.z * wv2.y + av.w * wv3.y;
            acc[j][2] += av.x * wv0.z + av.y * wv1.z + av.z * wv2.z + av.w * wv3.z;
            acc[j][3] += av.x * wv0.w + av.y * wv1.w + av.z * wv2.w + av.w * wv3.w;
        }
    }

    // Epilogue: + b2, write float4
    float4 bias = reinterpret_cast<const float4*>(b2)[tx];
    #pragma unroll
    for (int j = 0; j < 8; j++) {
        int gr = row0 + ty * 8 + j;
        if (gr < NN) {
            float4 o;
            o.x = acc[j][0] + bias.x;
            o.y = acc[j][1] + bias.y;
            o.z = acc[j][2] + bias.z;
            o.w = acc[j][3] + bias.w;
            reinterpret_cast<float4*>(out)[(size_t)gr * 32 + tx] = o;
        }
    }
}

// ---------------------------------------------------------------------------
// Launch: detect -> zero -> scatter -> gemm (default stream, capturable)
// Inputs (metadata order): x, edge_index, edge_weight, W1, b1, W2, b2, a, b
// ---------------------------------------------------------------------------
extern "C" void kernel_launch(void* const* d_in, const int* in_sizes, int n_in,
                              void* d_out, int out_size) {
    const float* x   = (const float*)d_in[0];
    const void*  ei  = d_in[1];
    const float* W2  = (const float*)d_in[5];
    const float* b2  = (const float*)d_in[6];
    float*       out = (float*)d_out;

    float* agg = nullptr;
    cudaGetSymbolAddress((void**)&agg, g_agg);

    // 0) detect edge_index element width (int32 vs int64)
    detect_kernel<<<1, 256>>>((const unsigned int*)ei);

    // 1) zero agg
    {
        int n4 = NN * FF / 4;                    // 1.6M float4
        int blocks = (n4 + 255) / 256;
        zero_kernel<<<blocks, 256>>>((float4*)agg, n4);
    }

    // 2) scatter: one warp per edge, 8 warps per block
    {
        int blocks = (EE + 7) / 8;               // 75000
        scatter_kernel<<<blocks, 256>>>(x, ei, agg);
    }

    // 3) GEMM + bias
    {
        int smem_bytes = (GEMM_ROWS * FF + FF * FF) * sizeof(float);  // 96 KB
        cudaFuncSetAttribute(gemm_kernel,
                             cudaFuncAttributeMaxDynamicSharedMemorySize,
                             smem_bytes);
        int blocks = (NN + GEMM_ROWS - 1) / GEMM_ROWS;  // 782
        gemm_kernel<<<blocks, 256, smem_bytes>>>(agg, W2, b2, out);
    }
}

// round 8
// speedup vs baseline: 1.0871x; 1.0871x over previous
#include <cuda_runtime.h>
#include <cuda_bf16.h>

// Problem constants (match reference_code)
#define NN 50000
#define EE 600000
#define FF 128   // F_IN == F_OUT == 128

// Scratch for the scatter-sum result (25.6 MB). Device globals are the
// sanctioned scratch mechanism (no allocations allowed).
__device__ float g_agg[(size_t)NN * FF];

// 1 if edge_index buffer holds int64 elements, 0 if int32.
__device__ int g_is64;

typedef unsigned long long u64;

// Packed fp32x2 helpers (sm_100+; ptxas never emits FFMA2 from plain C++)
__device__ __forceinline__ u64 pk2(float lo, float hi) {
    u64 r;
    asm("mov.b64 %0, {%1, %2};" : "=l"(r) : "f"(lo), "f"(hi));
    return r;
}
__device__ __forceinline__ void upk2(float& lo, float& hi, u64 v) {
    asm("mov.b64 {%0, %1}, %2;" : "=f"(lo), "=f"(hi) : "l"(v));
}
__device__ __forceinline__ void fma2(u64& d, u64 a, u64 b) {
    asm("fma.rn.f32x2 %0, %1, %2, %0;" : "+l"(d) : "l"(a), "l"(b));
}

// ---------------------------------------------------------------------------
// Kernel 1: zero the aggregation buffer; block 0 additionally detects the
// edge_index element width (int64 values < 50000 => all odd 32-bit words are
// zero high-halves; int32 => odd words are random node ids, OR != 0).
// ---------------------------------------------------------------------------
__global__ void zero_detect_kernel(float4* __restrict__ agg4, int n4,
                                   const unsigned int* __restrict__ ei_w) {
    int i = blockIdx.x * blockDim.x + threadIdx.x;
    if (i < n4) agg4[i] = make_float4(0.f, 0.f, 0.f, 0.f);

    if (blockIdx.x == 0) {
        __shared__ unsigned int red[256];
        unsigned int acc = 0;
        for (int s = threadIdx.x; s < 2048; s += 256)
            acc |= ei_w[2 * s + 1];
        red[threadIdx.x] = acc;
        __syncthreads();
        for (int s = 128; s > 0; s >>= 1) {
            if (threadIdx.x < s) red[threadIdx.x] |= red[threadIdx.x + s];
            __syncthreads();
        }
        if (threadIdx.x == 0) g_is64 = (red[0] == 0u) ? 1 : 0;
    }
}

// ---------------------------------------------------------------------------
// Kernel 2: edge scatter. One warp per edge.
// Lane l loads x[src][4l..4l+3] (LDG.128) and does a vector reduction
// (red.global.add.v4.f32 — fire-and-forget) into agg[dst].
// ---------------------------------------------------------------------------
__global__ void scatter_kernel(const float* __restrict__ x,
                               const void* __restrict__ eiv,
                               float* __restrict__ agg) {
    int warp = (blockIdx.x * blockDim.x + threadIdx.x) >> 5;
    int lane = threadIdx.x & 31;
    if (warp >= EE) return;

    int src, dst;
    if (g_is64) {
        const long long* ei = (const long long*)eiv;
        src = (int)ei[warp];
        dst = (int)ei[(long long)EE + warp];
    } else {
        const int* ei = (const int*)eiv;
        src = ei[warp];
        dst = ei[EE + warp];
    }
    if ((unsigned)src >= NN || (unsigned)dst >= NN) return;  // never on valid data

    const float4* xrow = reinterpret_cast<const float4*>(x + (size_t)src * FF);
    float4 v = xrow[lane];

    float* dp = agg + (size_t)dst * FF + lane * 4;
    asm volatile("red.global.add.v4.f32 [%0], {%1, %2, %3, %4};"
                 :: "l"(dp), "f"(v.x), "f"(v.y), "f"(v.z), "f"(v.w)
                 : "memory");
}

// ---------------------------------------------------------------------------
// Kernel 3: out[N,128] = agg[N,128] @ W2[128,128] + b2
// Block: 256 threads, 64 rows per block. Smem: A 64x128 + W2 128x128 = 96 KB.
// Thread (tx in [0,32), ty in [0,8)): cols 4*tx..4*tx+3, rows ty*8..ty*8+7.
// Inner math in packed fp32x2 (FFMA2): acc pairs adjacent columns, weight
// float4 splits into two b64 pairs, A-scalar duplicated via mov.b64 {a,a}.
// fma-pipe cost per 4-k iteration: 64 FFMA2 (vs 128 scalar FFMA before).
// ---------------------------------------------------------------------------
#define GEMM_ROWS 64

__global__ __launch_bounds__(256, 2)
void gemm_kernel(const float* __restrict__ agg,
                 const float* __restrict__ W2,
                 const float* __restrict__ b2,
                 float* __restrict__ out) {
    extern __shared__ float smem[];
    float* a_s = smem;                    // [64][128]
    float* w_s = smem + GEMM_ROWS * FF;   // [128][128]

    int tid = threadIdx.x;
    int tx  = tid & 31;
    int ty  = tid >> 5;
    int row0 = blockIdx.x * GEMM_ROWS;

    // Load A-tile (2048 float4)
    {
        const float4* a4g = reinterpret_cast<const float4*>(agg);
        float4* a4s = reinterpret_cast<float4*>(a_s);
        #pragma unroll
        for (int it = 0; it < (GEMM_ROWS * FF / 4) / 256; it++) {
            int idx = tid + it * 256;
            int r   = idx >> 5;
            int c4  = idx & 31;
            int gr  = row0 + r;
            float4 v = make_float4(0.f, 0.f, 0.f, 0.f);
            if (gr < NN) v = a4g[(size_t)gr * 32 + c4];
            a4s[idx] = v;
        }
    }
    // Load W2 (4096 float4)
    {
        const float4* w4g = reinterpret_cast<const float4*>(W2);
        float4* w4s = reinterpret_cast<float4*>(w_s);
        #pragma unroll
        for (int it = 0; it < (FF * FF / 4) / 256; it++) {
            int idx = tid + it * 256;
            w4s[idx] = w4g[idx];
        }
    }
    __syncthreads();

    // acc[j][p]: rows ty*8+j, column pair p (cols 4*tx+2p, 4*tx+2p+1)
    u64 acc[8][2];
    #pragma unroll
    for (int j = 0; j < 8; j++) {
        acc[j][0] = pk2(0.f, 0.f);
        acc[j][1] = pk2(0.f, 0.f);
    }

    const float4* a4s = reinterpret_cast<const float4*>(a_s);
    const float4* w4s = reinterpret_cast<const float4*>(w_s);

    #pragma unroll 4
    for (int k = 0; k < FF; k += 4) {
        float4 wv0 = w4s[(k + 0) * 32 + tx];
        float4 wv1 = w4s[(k + 1) * 32 + tx];
        float4 wv2 = w4s[(k + 2) * 32 + tx];
        float4 wv3 = w4s[(k + 3) * 32 + tx];
        u64 w0lo = pk2(wv0.x, wv0.y), w0hi = pk2(wv0.z, wv0.w);
        u64 w1lo = pk2(wv1.x, wv1.y), w1hi = pk2(wv1.z, wv1.w);
        u64 w2lo = pk2(wv2.x, wv2.y), w2hi = pk2(wv2.z, wv2.w);
        u64 w3lo = pk2(wv3.x, wv3.y), w3hi = pk2(wv3.z, wv3.w);

        #pragma unroll
        for (int j = 0; j < 8; j++) {
            int r = ty * 8 + j;
            float4 av = a4s[r * 32 + (k >> 2)];   // a[r][k..k+3] (broadcast)
            u64 ax = pk2(av.x, av.x);
            u64 ay = pk2(av.y, av.y);
            u64 az = pk2(av.z, av.z);
            u64 aw = pk2(av.w, av.w);
            fma2(acc[j][0], ax, w0lo);  fma2(acc[j][1], ax, w0hi);
            fma2(acc[j][0], ay, w1lo);  fma2(acc[j][1], ay, w1hi);
            fma2(acc[j][0], az, w2lo);  fma2(acc[j][1], az, w2hi);
            fma2(acc[j][0], aw, w3lo);  fma2(acc[j][1], aw, w3hi);
        }
    }

    // Epilogue: + b2, write float4
    float4 bias = reinterpret_cast<const float4*>(b2)[tx];
    #pragma unroll
    for (int j = 0; j < 8; j++) {
        int gr = row0 + ty * 8 + j;
        if (gr < NN) {
            float4 o;
            upk2(o.x, o.y, acc[j][0]);
            upk2(o.z, o.w, acc[j][1]);
            o.x += bias.x; o.y += bias.y; o.z += bias.z; o.w += bias.w;
            reinterpret_cast<float4*>(out)[(size_t)gr * 32 + tx] = o;
        }
    }
}

// ---------------------------------------------------------------------------
// Launch: zero+detect -> scatter -> gemm (default stream, capturable)
// Inputs (metadata order): x, edge_index, edge_weight, W1, b1, W2, b2, a, b
// ---------------------------------------------------------------------------
extern "C" void kernel_launch(void* const* d_in, const int* in_sizes, int n_in,
                              void* d_out, int out_size) {
    const float* x   = (const float*)d_in[0];
    const void*  ei  = d_in[1];
    const float* W2  = (const float*)d_in[5];
    const float* b2  = (const float*)d_in[6];
    float*       out = (float*)d_out;

    float* agg = nullptr;
    cudaGetSymbolAddress((void**)&agg, g_agg);

    // 1) zero agg + detect index dtype (fused)
    {
        int n4 = NN * FF / 4;                    // 1.6M float4
        int blocks = (n4 + 255) / 256;
        zero_detect_kernel<<<blocks, 256>>>((float4*)agg, n4,
                                            (const unsigned int*)ei);
    }

    // 2) scatter: one warp per edge, 8 warps per block
    {
        int blocks = (EE + 7) / 8;               // 75000
        scatter_kernel<<<blocks, 256>>>(x, ei, agg);
    }

    // 3) GEMM + bias (packed f32x2)
    {
        int smem_bytes = (GEMM_ROWS * FF + FF * FF) * sizeof(float);  // 96 KB
        cudaFuncSetAttribute(gemm_kernel,
                             cudaFuncAttributeMaxDynamicSharedMemorySize,
                             smem_bytes);
        int blocks = (NN + GEMM_ROWS - 1) / GEMM_ROWS;  // 782
        gemm_kernel<<<blocks, 256, smem_bytes>>>(agg, W2, b2, out);
    }
}